// round 1
// baseline (speedup 1.0000x reference)
#include <cuda_runtime.h>

// YOLO loss: pred/target [4096,14,14,30] fp32 -> scalar.
// Memory-bound reduction: 192.7 MB read, ~150 flops/cell.

#define S_DIM 14
#define BBOX 2
#define NCLS 20
#define BATCH 4096
#define FEAT (BBOX * 5 + NCLS)          // 30
#define NCELL (BATCH * S_DIM * S_DIM)   // 802816
#define THREADS 256
#define NBLOCKS (NCELL / THREADS)       // 3136 exactly

__device__ float g_partials[NBLOCKS];

__device__ __forceinline__ float iou_box(float ax, float ay, float aw, float ah,
                                         float bx, float by, float bw, float bh) {
    float a_x1 = ax - aw * 0.5f, a_y1 = ay - ah * 0.5f;
    float a_x2 = ax + aw * 0.5f, a_y2 = ay + ah * 0.5f;
    float b_x1 = bx - bw * 0.5f, b_y1 = by - bh * 0.5f;
    float b_x2 = bx + bw * 0.5f, b_y2 = by + bh * 0.5f;
    float iw = fmaxf(fminf(a_x2, b_x2) - fmaxf(a_x1, b_x1), 0.0f);
    float ih = fmaxf(fminf(a_y2, b_y2) - fmaxf(a_y1, b_y1), 0.0f);
    float inter = iw * ih;
    float a1 = (a_x2 - a_x1) * (a_y2 - a_y1);
    float a2 = (b_x2 - b_x1) * (b_y2 - b_y1);
    return inter / (a1 + a2 - inter + 1e-6f);
}

__global__ void __launch_bounds__(THREADS)
yolo_cell_kernel(const float* __restrict__ pred, const float* __restrict__ tgt) {
    int idx = blockIdx.x * blockDim.x + threadIdx.x;

    float p[FEAT], t[FEAT];
    {
        const float2* p2 = reinterpret_cast<const float2*>(pred + (size_t)idx * FEAT);
        const float2* t2 = reinterpret_cast<const float2*>(tgt  + (size_t)idx * FEAT);
#pragma unroll
        for (int i = 0; i < FEAT / 2; i++) {
            float2 v = p2[i]; p[2 * i] = v.x; p[2 * i + 1] = v.y;
        }
#pragma unroll
        for (int i = 0; i < FEAT / 2; i++) {
            float2 v = t2[i]; t[2 * i] = v.x; t[2 * i + 1] = v.y;
        }
    }

    // objectness: target[...,4] == target[...,9] == obj in {0,1}
    bool m  = t[4] > 0.0f;
    float mf = m ? 1.0f : 0.0f;

    // noobj confidence term (both boxes share the mask)
    float ce0 = p[4] - t[4]; ce0 *= ce0;
    float ce1 = p[9] - t[9]; ce1 *= ce1;
    float noobj_conf = m ? 0.0f : (ce0 + ce1);

    // per-box IoU, argmax with first-index tie break
    float iou0 = iou_box(p[0], p[1], p[2], p[3], t[0], t[1], t[2], t[3]);
    float iou1 = iou_box(p[5], p[6], p[7], p[8], t[5], t[6], t[7], t[8]);
    bool best1 = iou1 > iou0;

    // select best box with ternaries (no dynamic local indexing -> stays in regs)
    float pb0 = best1 ? p[5] : p[0];
    float pb1 = best1 ? p[6] : p[1];
    float pb2 = best1 ? p[7] : p[2];
    float pb3 = best1 ? p[8] : p[3];
    float pb4 = best1 ? p[9] : p[4];
    float tb0 = best1 ? t[5] : t[0];
    float tb1 = best1 ? t[6] : t[1];
    float tb2 = best1 ? t[7] : t[2];
    float tb3 = best1 ? t[8] : t[3];
    float tb4 = best1 ? t[9] : t[4];

    float dx = pb0 - tb0, dy = pb1 - tb1;
    float xy_loss = dx * dx + dy * dy;

    float pw = sqrtf(fabsf(pb2) + 1e-6f);
    float ph = sqrtf(fabsf(pb3) + 1e-6f);
    float tw = sqrtf(m ? tb2 : 1.0f);
    float th = sqrtf(m ? tb3 : 1.0f);
    float dw = pw - tw, dh = ph - th;
    float wh_loss = dw * dw + dh * dh;

    float coord_loss = xy_loss + wh_loss;

    float dobj = pb4 - tb4;
    float obj_loss = dobj * dobj;

    float nonbest = p[4] + p[9] - pb4;

    float cls = 0.0f;
#pragma unroll
    for (int c = 0; c < NCLS; c++) {
        float d = p[10 + c] - t[10 + c];
        cls += d * d;
    }

    // total = 5*coord + obj + 0.5*(noobj_conf + 0.5*mf*nonbest^2) + cls
    float loss = 5.0f * mf * coord_loss
               + mf * obj_loss
               + 0.5f * (noobj_conf + 0.5f * mf * nonbest * nonbest)
               + mf * cls;

    // ---- block reduction (deterministic) ----
    __shared__ float warp_sums[THREADS / 32];
#pragma unroll
    for (int off = 16; off > 0; off >>= 1)
        loss += __shfl_down_sync(0xFFFFFFFFu, loss, off);
    int lane = threadIdx.x & 31;
    int wid  = threadIdx.x >> 5;
    if (lane == 0) warp_sums[wid] = loss;
    __syncthreads();
    if (wid == 0) {
        float v = (lane < THREADS / 32) ? warp_sums[lane] : 0.0f;
#pragma unroll
        for (int off = 4; off > 0; off >>= 1)
            v += __shfl_down_sync(0xFFFFFFFFu, v, off);
        if (lane == 0) g_partials[blockIdx.x] = v;
    }
}

__global__ void __launch_bounds__(1024)
yolo_final_reduce(float* __restrict__ out) {
    __shared__ float warp_sums[32];
    float v = 0.0f;
    for (int i = threadIdx.x; i < NBLOCKS; i += 1024)
        v += g_partials[i];
#pragma unroll
    for (int off = 16; off > 0; off >>= 1)
        v += __shfl_down_sync(0xFFFFFFFFu, v, off);
    int lane = threadIdx.x & 31;
    int wid  = threadIdx.x >> 5;
    if (lane == 0) warp_sums[wid] = v;
    __syncthreads();
    if (wid == 0) {
        v = warp_sums[lane];
#pragma unroll
        for (int off = 16; off > 0; off >>= 1)
            v += __shfl_down_sync(0xFFFFFFFFu, v, off);
        if (lane == 0) out[0] = v / (float)BATCH;
    }
}

extern "C" void kernel_launch(void* const* d_in, const int* in_sizes, int n_in,
                              void* d_out, int out_size) {
    const float* pred = (const float*)d_in[0];
    const float* tgt  = (const float*)d_in[1];
    float* out = (float*)d_out;
    yolo_cell_kernel<<<NBLOCKS, THREADS>>>(pred, tgt);
    yolo_final_reduce<<<1, 1024>>>(out);
}